// round 2
// baseline (speedup 1.0000x reference)
#include <cuda_runtime.h>
#include <math.h>

// Problem constants
#define NB   256
#define NS   1024
#define NROWS (NB * NS)   // 262144

// Scratch (device globals; padded by one row for branch-free prefetch)
__device__ float g_u[(size_t)NROWS * 128 + 128];
__device__ float g_bx[(size_t)NROWS * 8 + 8];

// ---------- packed fp32x2 helpers (FFMA2 path, 2x fp32 rate on sm_103a) ----------
__device__ __forceinline__ unsigned long long pack2(float a) {
    unsigned long long r; unsigned int ia = __float_as_uint(a);
    asm("mov.b64 %0, {%1,%2};" : "=l"(r) : "r"(ia), "r"(ia));
    return r;
}
__device__ __forceinline__ unsigned long long ffma2(unsigned long long a,
                                                    unsigned long long b,
                                                    unsigned long long c) {
    unsigned long long d;
    asm("fma.rn.f32x2 %0, %1, %2, %3;" : "=l"(d) : "l"(a), "l"(b), "l"(c));
    return d;
}
__device__ __forceinline__ float2 unpack2(unsigned long long v) {
    unsigned int lo, hi;
    asm("mov.b64 {%0,%1}, %2;" : "=r"(lo), "=r"(hi) : "l"(v));
    return make_float2(__uint_as_float(lo), __uint_as_float(hi));
}
__device__ __forceinline__ float gelu_exact(float x) {
    return 0.5f * x * (1.0f + erff(x * 0.7071067811865475f));
}
__device__ __forceinline__ float sigmoidf_(float v) { return 1.0f / (1.0f + expf(-v)); }

// MUFU.TANH (sm_75+), 1 instruction, ~16 cyc
__device__ __forceinline__ float tanh_fast(float x) {
    float y; asm("tanh.approx.f32 %0, %1;" : "=f"(y) : "f"(x)); return y;
}
// tanh-form GELU with HW tanh (model err ~3e-4; damped by corr_scale path)
__device__ __forceinline__ float gelu_fast(float x) {
    float x2 = x * x;
    float inner = 0.7978845608f * x * fmaf(0.044715f, x2, 1.0f);
    float t = tanh_fast(inner);
    float hx = 0.5f * x;
    return fmaf(hx, t, hx);
}

// ============================================================================
// Phase 1 (unchanged from R1): per 64-row tile of (B*S):
//   h  = gelu(LN(x @ W1 + b1))          (h kept in SMEM only)
//   u  = h @ Wc1[5:133,:] + bc1  -> g_u
//   bx = h @ Winn + binn         -> g_bx
// ============================================================================
__global__ __launch_bounds__(256, 2)
void p1_kernel(const float* __restrict__ x,   const float* __restrict__ W1,
               const float* __restrict__ b1,  const float* __restrict__ ln_g,
               const float* __restrict__ ln_b, const float* __restrict__ Winn,
               const float* __restrict__ binn, const float* __restrict__ Wc1,
               const float* __restrict__ bc1)
{
    __shared__ float  Hs[64 * 132];
    __shared__ float2 Wp[16 * 64];
    __shared__ float  sB1[128], sLG[128], sLB[128], sBC1[128], sWinn[128 * 5], sBinn[5];

    const int tid = threadIdx.x;
    const int tx  = tid & 15;
    const int ty  = tid >> 4;
    const size_t row0 = (size_t)blockIdx.x * 64;

    if (tid < 128) {
        sB1[tid] = b1[tid];  sLG[tid] = ln_g[tid];
        sLB[tid] = ln_b[tid]; sBC1[tid] = bc1[tid];
    }
    if (tid < 5) sBinn[tid] = binn[tid];
    for (int i = tid; i < 640; i += 256) sWinn[i] = Winn[i];

    unsigned long long acc[4][4];
#pragma unroll
    for (int i = 0; i < 4; i++)
#pragma unroll
        for (int j = 0; j < 4; j++) acc[i][j] = 0ULL;

    float* Xs = Hs;

    // ---- stage 1: h = x @ W1 ----
    for (int k0 = 0; k0 < 128; k0 += 16) {
        __syncthreads();
        {
            int r = tid >> 2, q = tid & 3;
            float4 v = *(const float4*)(x + (row0 + r) * 128 + k0 + q * 4);
            Xs[(q*4+0)*65 + r] = v.x;
            Xs[(q*4+1)*65 + r] = v.y;
            Xs[(q*4+2)*65 + r] = v.z;
            Xs[(q*4+3)*65 + r] = v.w;
        }
        {
            int kk = tid >> 4, p0 = (tid & 15) * 4;
            const float* wr = W1 + (size_t)(k0 + kk) * 128 + p0 * 2;
            float4 v0 = *(const float4*)(wr);
            float4 v1 = *(const float4*)(wr + 4);
            Wp[kk*64 + p0 + 0] = make_float2(v0.x, v0.y);
            Wp[kk*64 + p0 + 1] = make_float2(v0.z, v0.w);
            Wp[kk*64 + p0 + 2] = make_float2(v1.x, v1.y);
            Wp[kk*64 + p0 + 3] = make_float2(v1.z, v1.w);
        }
        __syncthreads();
#pragma unroll
        for (int kk = 0; kk < 16; kk++) {
            unsigned long long ap[4], bp[4];
#pragma unroll
            for (int rr = 0; rr < 4; rr++) ap[rr] = pack2(Xs[kk*65 + ty*4 + rr]);
#pragma unroll
            for (int cc = 0; cc < 4; cc++)
                bp[cc] = *(const unsigned long long*)&Wp[kk*64 + cc*16 + tx];
#pragma unroll
            for (int rr = 0; rr < 4; rr++)
#pragma unroll
                for (int cc = 0; cc < 4; cc++)
                    acc[rr][cc] = ffma2(ap[rr], bp[cc], acc[rr][cc]);
        }
    }
    __syncthreads();

#pragma unroll
    for (int rr = 0; rr < 4; rr++) {
        int r = ty*4 + rr;
#pragma unroll
        for (int cc = 0; cc < 4; cc++) {
            int c = (cc*16 + tx) * 2;
            float2 hv = unpack2(acc[rr][cc]);
            *(float2*)&Hs[r*132 + c] = make_float2(hv.x + sB1[c], hv.y + sB1[c+1]);
        }
    }
    __syncthreads();

    // ---- LayerNorm + exact GELU ----
    {
        int warp = tid >> 5, lane = tid & 31;
        for (int r = warp; r < 64; r += 8) {
            float4 v = *(const float4*)&Hs[r*132 + lane*4];
            float s = v.x + v.y + v.z + v.w;
#pragma unroll
            for (int off = 16; off; off >>= 1) s += __shfl_xor_sync(0xffffffffu, s, off);
            float mu = s * 0.0078125f;
            float dx = v.x - mu, dy = v.y - mu, dz = v.z - mu, dw = v.w - mu;
            float q = dx*dx + dy*dy + dz*dz + dw*dw;
#pragma unroll
            for (int off = 16; off; off >>= 1) q += __shfl_xor_sync(0xffffffffu, q, off);
            float rs = rsqrtf(q * 0.0078125f + 1e-5f);
            int c = lane * 4;
            float h0 = dx*rs*sLG[c+0] + sLB[c+0];
            float h1 = dy*rs*sLG[c+1] + sLB[c+1];
            float h2 = dz*rs*sLG[c+2] + sLB[c+2];
            float h3 = dw*rs*sLG[c+3] + sLB[c+3];
            *(float4*)&Hs[r*132 + c] =
                make_float4(gelu_exact(h0), gelu_exact(h1), gelu_exact(h2), gelu_exact(h3));
        }
    }
    __syncthreads();

    // ---- bx = h @ Winn + binn ----
    for (int idx = tid; idx < 64 * 5; idx += 256) {
        int r = idx / 5, c = idx - r * 5;
        float a = sBinn[c];
#pragma unroll 4
        for (int k = 0; k < 128; k++) a += Hs[r*132 + k] * sWinn[k*5 + c];
        g_bx[(row0 + r) * 8 + c] = a;
    }

    // ---- stage 2: u = h @ Wc1[5:,:] + bc1 ----
#pragma unroll
    for (int i = 0; i < 4; i++)
#pragma unroll
        for (int j = 0; j < 4; j++) acc[i][j] = 0ULL;

    for (int k0 = 0; k0 < 128; k0 += 16) {
        __syncthreads();
        {
            int kk = tid >> 4, p0 = (tid & 15) * 4;
            const float* wr = Wc1 + (size_t)(5 + k0 + kk) * 128 + p0 * 2;
            float4 v0 = *(const float4*)(wr);
            float4 v1 = *(const float4*)(wr + 4);
            Wp[kk*64 + p0 + 0] = make_float2(v0.x, v0.y);
            Wp[kk*64 + p0 + 1] = make_float2(v0.z, v0.w);
            Wp[kk*64 + p0 + 2] = make_float2(v1.x, v1.y);
            Wp[kk*64 + p0 + 3] = make_float2(v1.z, v1.w);
        }
        __syncthreads();
#pragma unroll
        for (int kk = 0; kk < 16; kk++) {
            unsigned long long ap[4], bp[4];
#pragma unroll
            for (int rr = 0; rr < 4; rr++) ap[rr] = pack2(Hs[(ty*4+rr)*132 + k0 + kk]);
#pragma unroll
            for (int cc = 0; cc < 4; cc++)
                bp[cc] = *(const unsigned long long*)&Wp[kk*64 + cc*16 + tx];
#pragma unroll
            for (int rr = 0; rr < 4; rr++)
#pragma unroll
                for (int cc = 0; cc < 4; cc++)
                    acc[rr][cc] = ffma2(ap[rr], bp[cc], acc[rr][cc]);
        }
    }
#pragma unroll
    for (int rr = 0; rr < 4; rr++) {
        size_t r = row0 + ty*4 + rr;
#pragma unroll
        for (int cc = 0; cc < 4; cc++) {
            int c = (cc*16 + tx) * 2;
            float2 uv = unpack2(acc[rr][cc]);
            *(float2*)&g_u[r*128 + c] = make_float2(uv.x + sBC1[c], uv.y + sBC1[c+1]);
        }
    }
}

// ============================================================================
// Phase 2: sequential scan. One warp per TWO batches (b, b+128) — two
// independent dependency chains interleaved in one warp to hide the
// shfl-butterfly + MUFU latency chain. 128 blocks x 32 threads (1 warp/SM).
// All transcendentals are single MUFU instructions.
// ============================================================================
struct StepConsts {
    float aL, aT, gc, gs, ngs, aR, cs;
};

__global__ __launch_bounds__(32)
void p2_kernel(const float* __restrict__ Wc1, const float* __restrict__ Wc2,
               const float* __restrict__ bc2, const float* __restrict__ corr_scale,
               const float* __restrict__ raw_aL, const float* __restrict__ raw_aT,
               const float* __restrict__ raw_g,  const float* __restrict__ raw_aR,
               const float* __restrict__ omega,  float* __restrict__ out)
{
    const int lane = threadIdx.x & 31;
    const int bA = blockIdx.x;          // batch A
    const int bB = blockIdx.x + 128;    // batch B

    StepConsts C;
    C.aL = sigmoidf_(raw_aL[0]) * 0.15f + 0.85f;
    C.aT = sigmoidf_(raw_aT[0]) * 0.25f + 0.70f;
    float gg = sigmoidf_(raw_g[0]) * 0.20f + 0.80f;
    C.aR = sigmoidf_(raw_aR[0]) * 0.40f;
    float om = omega[0];
    C.gc = gg * cosf(om); C.gs = gg * sinf(om); C.ngs = -C.gs;
    C.cs = corr_scale[0];

    const int c0 = lane * 4;
    float Ws[5][4], Wo[4][5], bb[5];
#pragma unroll
    for (int i = 0; i < 5; i++)
#pragma unroll
        for (int c = 0; c < 4; c++) Ws[i][c] = Wc1[i*128 + c0 + c];
#pragma unroll
    for (int c = 0; c < 4; c++)
#pragma unroll
        for (int k = 0; k < 5; k++) Wo[c][k] = Wc2[(c0 + c)*5 + k];
#pragma unroll
    for (int k = 0; k < 5; k++) bb[k] = bc2[k];

    float sA[5], sB[5];
#pragma unroll
    for (int k = 0; k < 5; k++) { sA[k] = 0.f; sB[k] = 0.f; }

    const float4* upA = (const float4*)(g_u + (size_t)bA * NS * 128);
    const float4* upB = (const float4*)(g_u + (size_t)bB * NS * 128);
    const float*  bxA = g_bx + (size_t)bA * NS * 8;
    const float*  bxB = g_bx + (size_t)bB * NS * 8;

    float4 uA = upA[lane], uB = upB[lane];
    float4 xA = *(const float4*)(bxA); float xA4 = bxA[4];
    float4 xB = *(const float4*)(bxB); float xB4 = bxB[4];

    for (int t = 0; t < NS; t++) {
        // branch-free prefetch of t+1 (arrays padded by one row)
        const int pf = (t + 1) * 32 + lane;
        float4 uAn = upA[pf], uBn = upB[pf];
        const float* bAn = bxA + (t + 1) * 8;
        const float* bBn = bxB + (t + 1) * 8;
        float4 xAn = *(const float4*)bAn; float xA4n = bAn[4];
        float4 xBn = *(const float4*)bBn; float xB4n = bBn[4];

        // ---- batch A ----
        float lA[5];
        lA[0] = fmaf(sA[0], C.aL, xA.x);
        lA[1] = fmaf(sA[1], C.aT, xA.y);
        lA[2] = fmaf(sA[2], C.gc, fmaf(sA[3], C.gs,  xA.z));
        lA[3] = fmaf(sA[3], C.gc, fmaf(sA[2], C.ngs, xA.w));
        lA[4] = fmaf(sA[4], C.aR, xA4);
        // ---- batch B ----
        float lB[5];
        lB[0] = fmaf(sB[0], C.aL, xB.x);
        lB[1] = fmaf(sB[1], C.aT, xB.y);
        lB[2] = fmaf(sB[2], C.gc, fmaf(sB[3], C.gs,  xB.z));
        lB[3] = fmaf(sB[3], C.gc, fmaf(sB[2], C.ngs, xB.w));
        lB[4] = fmaf(sB[4], C.aR, xB4);

        float mA[4], mB[4];
        {
            const float ua[4] = {uA.x, uA.y, uA.z, uA.w};
            const float ub[4] = {uB.x, uB.y, uB.z, uB.w};
#pragma unroll
            for (int c = 0; c < 4; c++) {
                float a = ua[c], b = ub[c];
#pragma unroll
                for (int i = 0; i < 5; i++) {
                    a = fmaf(lA[i], Ws[i][c], a);
                    b = fmaf(lB[i], Ws[i][c], b);
                }
                mA[c] = gelu_fast(a);
                mB[c] = gelu_fast(b);
            }
        }

        float pA[5], pB[5];
#pragma unroll
        for (int k = 0; k < 5; k++) {
            float a = mA[0] * Wo[0][k], b = mB[0] * Wo[0][k];
#pragma unroll
            for (int c = 1; c < 4; c++) {
                a = fmaf(mA[c], Wo[c][k], a);
                b = fmaf(mB[c], Wo[c][k], b);
            }
            pA[k] = a; pB[k] = b;
        }
#pragma unroll
        for (int off = 16; off; off >>= 1) {
#pragma unroll
            for (int k = 0; k < 5; k++) {
                pA[k] += __shfl_xor_sync(0xffffffffu, pA[k], off);
                pB[k] += __shfl_xor_sync(0xffffffffu, pB[k], off);
            }
        }
#pragma unroll
        for (int k = 0; k < 5; k++) {
            sA[k] = fmaf(C.cs, tanh_fast(pA[k] + bb[k]), lA[k]);
            sB[k] = fmaf(C.cs, tanh_fast(pB[k] + bb[k]), lB[k]);
        }

        uA = uAn; uB = uBn; xA = xAn; xA4 = xA4n; xB = xBn; xB4 = xB4n;
    }

    if (lane == 0) {
#pragma unroll
        for (int k = 0; k < 5; k++) {
            out[bA*5 + k] = sA[k];
            out[bB*5 + k] = sB[k];
        }
    }
}

// ============================================================================
extern "C" void kernel_launch(void* const* d_in, const int* in_sizes, int n_in,
                              void* d_out, int out_size)
{
    (void)in_sizes; (void)n_in; (void)out_size;
    const float* x    = (const float*)d_in[0];
    const float* W1   = (const float*)d_in[1];
    const float* b1   = (const float*)d_in[2];
    const float* ln_g = (const float*)d_in[3];
    const float* ln_b = (const float*)d_in[4];
    const float* Winn = (const float*)d_in[5];
    const float* binn = (const float*)d_in[6];
    const float* Wc1  = (const float*)d_in[7];
    const float* bc1  = (const float*)d_in[8];
    const float* Wc2  = (const float*)d_in[9];
    const float* bc2  = (const float*)d_in[10];
    const float* cscl = (const float*)d_in[11];
    const float* raL  = (const float*)d_in[12];
    const float* raT  = (const float*)d_in[13];
    const float* rg   = (const float*)d_in[14];
    const float* raR  = (const float*)d_in[15];
    const float* om   = (const float*)d_in[16];

    p1_kernel<<<NROWS / 64, 256>>>(x, W1, b1, ln_g, ln_b, Winn, binn, Wc1, bc1);
    p2_kernel<<<NB / 2, 32>>>(Wc1, Wc2, bc2, cscl, raL, raT, rg, raR, om, (float*)d_out);
}

// round 3
// speedup vs baseline: 1.7508x; 1.7508x over previous
#include <cuda_runtime.h>
#include <math.h>

// Problem constants
#define NB   256
#define NS   1024
#define NROWS (NB * NS)   // 262144

// Scratch (device globals; padded by 4 rows for branch-free depth-4 prefetch)
__device__ float g_u[(size_t)NROWS * 128 + 512];
__device__ float g_bx[(size_t)NROWS * 8 + 32];

// ---------- packed fp32x2 helpers (FFMA2 path, 2x fp32 rate on sm_103a) ----------
__device__ __forceinline__ unsigned long long pack2(float a) {
    unsigned long long r; unsigned int ia = __float_as_uint(a);
    asm("mov.b64 %0, {%1,%2};" : "=l"(r) : "r"(ia), "r"(ia));
    return r;
}
__device__ __forceinline__ unsigned long long ffma2(unsigned long long a,
                                                    unsigned long long b,
                                                    unsigned long long c) {
    unsigned long long d;
    asm("fma.rn.f32x2 %0, %1, %2, %3;" : "=l"(d) : "l"(a), "l"(b), "l"(c));
    return d;
}
__device__ __forceinline__ float2 unpack2(unsigned long long v) {
    unsigned int lo, hi;
    asm("mov.b64 {%0,%1}, %2;" : "=r"(lo), "=r"(hi) : "l"(v));
    return make_float2(__uint_as_float(lo), __uint_as_float(hi));
}
__device__ __forceinline__ float gelu_exact(float x) {
    return 0.5f * x * (1.0f + erff(x * 0.7071067811865475f));
}
__device__ __forceinline__ float sigmoidf_(float v) { return 1.0f / (1.0f + expf(-v)); }

// MUFU.TANH (1 instruction, ~16 cyc)
__device__ __forceinline__ float tanh_fast(float x) {
    float y; asm("tanh.approx.f32 %0, %1;" : "=f"(y) : "f"(x)); return y;
}
// tanh-form GELU with HW tanh (err ~3e-4 pre-damping; verified rel_err 3.5e-6 end-to-end)
__device__ __forceinline__ float gelu_fast(float x) {
    float x2 = x * x;
    float inner = 0.7978845608f * x * fmaf(0.044715f, x2, 1.0f);
    float t = tanh_fast(inner);
    float hx = 0.5f * x;
    return fmaf(hx, t, hx);
}

// ============================================================================
// Phase 1 (unchanged): per 64-row tile of (B*S):
//   h  = gelu(LN(x @ W1 + b1))          (h kept in SMEM only)
//   u  = h @ Wc1[5:133,:] + bc1  -> g_u
//   bx = h @ Winn + binn         -> g_bx
// ============================================================================
__global__ __launch_bounds__(256, 2)
void p1_kernel(const float* __restrict__ x,   const float* __restrict__ W1,
               const float* __restrict__ b1,  const float* __restrict__ ln_g,
               const float* __restrict__ ln_b, const float* __restrict__ Winn,
               const float* __restrict__ binn, const float* __restrict__ Wc1,
               const float* __restrict__ bc1)
{
    __shared__ float  Hs[64 * 132];
    __shared__ float2 Wp[16 * 64];
    __shared__ float  sB1[128], sLG[128], sLB[128], sBC1[128], sWinn[128 * 5], sBinn[5];

    const int tid = threadIdx.x;
    const int tx  = tid & 15;
    const int ty  = tid >> 4;
    const size_t row0 = (size_t)blockIdx.x * 64;

    if (tid < 128) {
        sB1[tid] = b1[tid];  sLG[tid] = ln_g[tid];
        sLB[tid] = ln_b[tid]; sBC1[tid] = bc1[tid];
    }
    if (tid < 5) sBinn[tid] = binn[tid];
    for (int i = tid; i < 640; i += 256) sWinn[i] = Winn[i];

    unsigned long long acc[4][4];
#pragma unroll
    for (int i = 0; i < 4; i++)
#pragma unroll
        for (int j = 0; j < 4; j++) acc[i][j] = 0ULL;

    float* Xs = Hs;

    // ---- stage 1: h = x @ W1 ----
    for (int k0 = 0; k0 < 128; k0 += 16) {
        __syncthreads();
        {
            int r = tid >> 2, q = tid & 3;
            float4 v = *(const float4*)(x + (row0 + r) * 128 + k0 + q * 4);
            Xs[(q*4+0)*65 + r] = v.x;
            Xs[(q*4+1)*65 + r] = v.y;
            Xs[(q*4+2)*65 + r] = v.z;
            Xs[(q*4+3)*65 + r] = v.w;
        }
        {
            int kk = tid >> 4, p0 = (tid & 15) * 4;
            const float* wr = W1 + (size_t)(k0 + kk) * 128 + p0 * 2;
            float4 v0 = *(const float4*)(wr);
            float4 v1 = *(const float4*)(wr + 4);
            Wp[kk*64 + p0 + 0] = make_float2(v0.x, v0.y);
            Wp[kk*64 + p0 + 1] = make_float2(v0.z, v0.w);
            Wp[kk*64 + p0 + 2] = make_float2(v1.x, v1.y);
            Wp[kk*64 + p0 + 3] = make_float2(v1.z, v1.w);
        }
        __syncthreads();
#pragma unroll
        for (int kk = 0; kk < 16; kk++) {
            unsigned long long ap[4], bp[4];
#pragma unroll
            for (int rr = 0; rr < 4; rr++) ap[rr] = pack2(Xs[kk*65 + ty*4 + rr]);
#pragma unroll
            for (int cc = 0; cc < 4; cc++)
                bp[cc] = *(const unsigned long long*)&Wp[kk*64 + cc*16 + tx];
#pragma unroll
            for (int rr = 0; rr < 4; rr++)
#pragma unroll
                for (int cc = 0; cc < 4; cc++)
                    acc[rr][cc] = ffma2(ap[rr], bp[cc], acc[rr][cc]);
        }
    }
    __syncthreads();

#pragma unroll
    for (int rr = 0; rr < 4; rr++) {
        int r = ty*4 + rr;
#pragma unroll
        for (int cc = 0; cc < 4; cc++) {
            int c = (cc*16 + tx) * 2;
            float2 hv = unpack2(acc[rr][cc]);
            *(float2*)&Hs[r*132 + c] = make_float2(hv.x + sB1[c], hv.y + sB1[c+1]);
        }
    }
    __syncthreads();

    // ---- LayerNorm + exact GELU ----
    {
        int warp = tid >> 5, lane = tid & 31;
        for (int r = warp; r < 64; r += 8) {
            float4 v = *(const float4*)&Hs[r*132 + lane*4];
            float s = v.x + v.y + v.z + v.w;
#pragma unroll
            for (int off = 16; off; off >>= 1) s += __shfl_xor_sync(0xffffffffu, s, off);
            float mu = s * 0.0078125f;
            float dx = v.x - mu, dy = v.y - mu, dz = v.z - mu, dw = v.w - mu;
            float q = dx*dx + dy*dy + dz*dz + dw*dw;
#pragma unroll
            for (int off = 16; off; off >>= 1) q += __shfl_xor_sync(0xffffffffu, q, off);
            float rs = rsqrtf(q * 0.0078125f + 1e-5f);
            int c = lane * 4;
            float h0 = dx*rs*sLG[c+0] + sLB[c+0];
            float h1 = dy*rs*sLG[c+1] + sLB[c+1];
            float h2 = dz*rs*sLG[c+2] + sLB[c+2];
            float h3 = dw*rs*sLG[c+3] + sLB[c+3];
            *(float4*)&Hs[r*132 + c] =
                make_float4(gelu_exact(h0), gelu_exact(h1), gelu_exact(h2), gelu_exact(h3));
        }
    }
    __syncthreads();

    // ---- bx = h @ Winn + binn ----
    for (int idx = tid; idx < 64 * 5; idx += 256) {
        int r = idx / 5, c = idx - r * 5;
        float a = sBinn[c];
#pragma unroll 4
        for (int k = 0; k < 128; k++) a += Hs[r*132 + k] * sWinn[k*5 + c];
        g_bx[(row0 + r) * 8 + c] = a;
    }

    // ---- stage 2: u = h @ Wc1[5:,:] + bc1 ----
#pragma unroll
    for (int i = 0; i < 4; i++)
#pragma unroll
        for (int j = 0; j < 4; j++) acc[i][j] = 0ULL;

    for (int k0 = 0; k0 < 128; k0 += 16) {
        __syncthreads();
        {
            int kk = tid >> 4, p0 = (tid & 15) * 4;
            const float* wr = Wc1 + (size_t)(5 + k0 + kk) * 128 + p0 * 2;
            float4 v0 = *(const float4*)(wr);
            float4 v1 = *(const float4*)(wr + 4);
            Wp[kk*64 + p0 + 0] = make_float2(v0.x, v0.y);
            Wp[kk*64 + p0 + 1] = make_float2(v0.z, v0.w);
            Wp[kk*64 + p0 + 2] = make_float2(v1.x, v1.y);
            Wp[kk*64 + p0 + 3] = make_float2(v1.z, v1.w);
        }
        __syncthreads();
#pragma unroll
        for (int kk = 0; kk < 16; kk++) {
            unsigned long long ap[4], bp[4];
#pragma unroll
            for (int rr = 0; rr < 4; rr++) ap[rr] = pack2(Hs[(ty*4+rr)*132 + k0 + kk]);
#pragma unroll
            for (int cc = 0; cc < 4; cc++)
                bp[cc] = *(const unsigned long long*)&Wp[kk*64 + cc*16 + tx];
#pragma unroll
            for (int rr = 0; rr < 4; rr++)
#pragma unroll
                for (int cc = 0; cc < 4; cc++)
                    acc[rr][cc] = ffma2(ap[rr], bp[cc], acc[rr][cc]);
        }
    }
#pragma unroll
    for (int rr = 0; rr < 4; rr++) {
        size_t r = row0 + ty*4 + rr;
#pragma unroll
        for (int cc = 0; cc < 4; cc++) {
            int c = (cc*16 + tx) * 2;
            float2 uv = unpack2(acc[rr][cc]);
            *(float2*)&g_u[r*128 + c] = make_float2(uv.x + sBC1[c], uv.y + sBC1[c+1]);
        }
    }
}

// ============================================================================
// Phase 2: sequential scan. One warp per batch (64 blocks x 4 warps = 256),
// depth-4 software-pipelined register prefetch of (u, bx) to cover DRAM
// latency (~4 steps x ~230 cyc ≈ 900+ cyc > 577-900 cyc LDG-DRAM).
// All transcendentals are single MUFU instructions.
// ============================================================================
__global__ void __launch_bounds__(128)
p2_kernel(const float* __restrict__ Wc1, const float* __restrict__ Wc2,
          const float* __restrict__ bc2, const float* __restrict__ corr_scale,
          const float* __restrict__ raw_aL, const float* __restrict__ raw_aT,
          const float* __restrict__ raw_g,  const float* __restrict__ raw_aR,
          const float* __restrict__ omega,  float* __restrict__ out)
{
    const int warp = threadIdx.x >> 5, lane = threadIdx.x & 31;
    const int b = blockIdx.x * 4 + warp;

    const float aL = sigmoidf_(raw_aL[0]) * 0.15f + 0.85f;
    const float aT = sigmoidf_(raw_aT[0]) * 0.25f + 0.70f;
    const float gg = sigmoidf_(raw_g[0])  * 0.20f + 0.80f;
    const float aR = sigmoidf_(raw_aR[0]) * 0.40f;
    const float om = omega[0];
    const float gc = gg * cosf(om), gs = gg * sinf(om), ngs = -gs;
    const float cs = corr_scale[0];

    const int c0 = lane * 4;
    float Ws[5][4], Wo[4][5], bb[5];
#pragma unroll
    for (int i = 0; i < 5; i++)
#pragma unroll
        for (int c = 0; c < 4; c++) Ws[i][c] = Wc1[i*128 + c0 + c];
#pragma unroll
    for (int c = 0; c < 4; c++)
#pragma unroll
        for (int k = 0; k < 5; k++) Wo[c][k] = Wc2[(c0 + c)*5 + k];
#pragma unroll
    for (int k = 0; k < 5; k++) bb[k] = bc2[k];

    float s0 = 0.f, s1 = 0.f, s2 = 0.f, s3 = 0.f, s4 = 0.f;
    const float4* up  = (const float4*)(g_u + (size_t)b * NS * 128);
    const float*  bxp = g_bx + (size_t)b * NS * 8;

    // depth-4 rotating prefetch buffers
    float4 ub[4], xb[4]; float x4b[4];
#pragma unroll
    for (int j = 0; j < 4; j++) {
        ub[j]  = up[j * 32 + lane];
        xb[j]  = *(const float4*)(bxp + j * 8);
        x4b[j] = bxp[j * 8 + 4];
    }

    for (int t0 = 0; t0 < NS; t0 += 4) {
#pragma unroll
        for (int j = 0; j < 4; j++) {
            const int t = t0 + j;
            // consume slot j
            const float4 u = ub[j];
            const float4 x = xb[j];
            const float  x4 = x4b[j];
            // refill slot j with t+4 (arrays padded by 4 rows -> branch-free)
            ub[j]  = up[(t + 4) * 32 + lane];
            xb[j]  = *(const float4*)(bxp + (t + 4) * 8);
            x4b[j] = bxp[(t + 4) * 8 + 4];

            float l0 = fmaf(s0, aL, x.x);
            float l1 = fmaf(s1, aT, x.y);
            float l2 = fmaf(s2, gc, fmaf(s3, gs,  x.z));
            float l3 = fmaf(s3, gc, fmaf(s2, ngs, x.w));
            float l4 = fmaf(s4, aR, x4);

            float a0 = u.x, a1 = u.y, a2 = u.z, a3 = u.w;
            a0 = fmaf(l0, Ws[0][0], a0); a1 = fmaf(l0, Ws[0][1], a1);
            a2 = fmaf(l0, Ws[0][2], a2); a3 = fmaf(l0, Ws[0][3], a3);
            a0 = fmaf(l1, Ws[1][0], a0); a1 = fmaf(l1, Ws[1][1], a1);
            a2 = fmaf(l1, Ws[1][2], a2); a3 = fmaf(l1, Ws[1][3], a3);
            a0 = fmaf(l2, Ws[2][0], a0); a1 = fmaf(l2, Ws[2][1], a1);
            a2 = fmaf(l2, Ws[2][2], a2); a3 = fmaf(l2, Ws[2][3], a3);
            a0 = fmaf(l3, Ws[3][0], a0); a1 = fmaf(l3, Ws[3][1], a1);
            a2 = fmaf(l3, Ws[3][2], a2); a3 = fmaf(l3, Ws[3][3], a3);
            a0 = fmaf(l4, Ws[4][0], a0); a1 = fmaf(l4, Ws[4][1], a1);
            a2 = fmaf(l4, Ws[4][2], a2); a3 = fmaf(l4, Ws[4][3], a3);

            float m0 = gelu_fast(a0);
            float m1 = gelu_fast(a1);
            float m2 = gelu_fast(a2);
            float m3 = gelu_fast(a3);

            float p0 = m0*Wo[0][0], p1 = m0*Wo[0][1], p2 = m0*Wo[0][2],
                  p3 = m0*Wo[0][3], p4 = m0*Wo[0][4];
            p0 = fmaf(m1, Wo[1][0], p0); p1 = fmaf(m1, Wo[1][1], p1);
            p2 = fmaf(m1, Wo[1][2], p2); p3 = fmaf(m1, Wo[1][3], p3);
            p4 = fmaf(m1, Wo[1][4], p4);
            p0 = fmaf(m2, Wo[2][0], p0); p1 = fmaf(m2, Wo[2][1], p1);
            p2 = fmaf(m2, Wo[2][2], p2); p3 = fmaf(m2, Wo[2][3], p3);
            p4 = fmaf(m2, Wo[2][4], p4);
            p0 = fmaf(m3, Wo[3][0], p0); p1 = fmaf(m3, Wo[3][1], p1);
            p2 = fmaf(m3, Wo[3][2], p2); p3 = fmaf(m3, Wo[3][3], p3);
            p4 = fmaf(m3, Wo[3][4], p4);

#pragma unroll
            for (int off = 16; off; off >>= 1) {
                p0 += __shfl_xor_sync(0xffffffffu, p0, off);
                p1 += __shfl_xor_sync(0xffffffffu, p1, off);
                p2 += __shfl_xor_sync(0xffffffffu, p2, off);
                p3 += __shfl_xor_sync(0xffffffffu, p3, off);
                p4 += __shfl_xor_sync(0xffffffffu, p4, off);
            }
            s0 = fmaf(cs, tanh_fast(p0 + bb[0]), l0);
            s1 = fmaf(cs, tanh_fast(p1 + bb[1]), l1);
            s2 = fmaf(cs, tanh_fast(p2 + bb[2]), l2);
            s3 = fmaf(cs, tanh_fast(p3 + bb[3]), l3);
            s4 = fmaf(cs, tanh_fast(p4 + bb[4]), l4);
        }
    }

    if (lane == 0) {
        out[b*5+0] = s0; out[b*5+1] = s1; out[b*5+2] = s2;
        out[b*5+3] = s3; out[b*5+4] = s4;
    }
}

// ============================================================================
extern "C" void kernel_launch(void* const* d_in, const int* in_sizes, int n_in,
                              void* d_out, int out_size)
{
    (void)in_sizes; (void)n_in; (void)out_size;
    const float* x    = (const float*)d_in[0];
    const float* W1   = (const float*)d_in[1];
    const float* b1   = (const float*)d_in[2];
    const float* ln_g = (const float*)d_in[3];
    const float* ln_b = (const float*)d_in[4];
    const float* Winn = (const float*)d_in[5];
    const float* binn = (const float*)d_in[6];
    const float* Wc1  = (const float*)d_in[7];
    const float* bc1  = (const float*)d_in[8];
    const float* Wc2  = (const float*)d_in[9];
    const float* bc2  = (const float*)d_in[10];
    const float* cscl = (const float*)d_in[11];
    const float* raL  = (const float*)d_in[12];
    const float* raT  = (const float*)d_in[13];
    const float* rg   = (const float*)d_in[14];
    const float* raR  = (const float*)d_in[15];
    const float* om   = (const float*)d_in[16];

    p1_kernel<<<NROWS / 64, 256>>>(x, W1, b1, ln_g, ln_b, Winn, binn, Wc1, bc1);
    p2_kernel<<<NB / 4, 128>>>(Wc1, Wc2, bc2, cscl, raL, raT, rg, raR, om, (float*)d_out);
}

// round 5
// speedup vs baseline: 1.8079x; 1.0326x over previous
#include <cuda_runtime.h>
#include <cuda_bf16.h>
#include <math.h>
#include <stdint.h>

// Problem constants
#define NB   256
#define NS   1024
#define NROWS (NB * NS)   // 262144

// Scratch (device globals; padded by 4 rows for branch-free depth-4 prefetch)
__device__ float g_u[(size_t)NROWS * 128 + 512];
__device__ float g_bx[(size_t)NROWS * 8 + 32];
// bf16 hi/lo weight images, transposed to [n][k], row stride 136 elements
__device__ __nv_bfloat16 g_B1h[17408], g_B1l[17408], g_B2h[17408], g_B2l[17408];

// ---------------- math helpers ----------------
__device__ __forceinline__ float gelu_exact(float x) {
    return 0.5f * x * (1.0f + erff(x * 0.7071067811865475f));
}
__device__ __forceinline__ float sigmoidf_(float v) { return 1.0f / (1.0f + expf(-v)); }
__device__ __forceinline__ float tanh_fast(float x) {
    float y; asm("tanh.approx.f32 %0, %1;" : "=f"(y) : "f"(x)); return y;
}
__device__ __forceinline__ float gelu_fast(float x) {
    float x2 = x * x;
    float inner = 0.7978845608f * x * fmaf(0.044715f, x2, 1.0f);
    float t = tanh_fast(inner);
    float hx = 0.5f * x;
    return fmaf(hx, t, hx);
}
__device__ __forceinline__ unsigned pack_b2(__nv_bfloat16 a, __nv_bfloat16 b) {
    __nv_bfloat162 t = __halves2bfloat162(a, b);
    return *reinterpret_cast<unsigned*>(&t);
}
// pack two floats to bf16x2 (hi) and residual bf16x2 (lo)
__device__ __forceinline__ void split2(float a, float b, unsigned& hi, unsigned& lo) {
    __nv_bfloat16 ha = __float2bfloat16(a), hb = __float2bfloat16(b);
    __nv_bfloat16 la = __float2bfloat16(a - __bfloat162float(ha));
    __nv_bfloat16 lb = __float2bfloat16(b - __bfloat162float(hb));
    hi = pack_b2(ha, hb); lo = pack_b2(la, lb);
}

#define MMA16816(c, a0, a1, a2, a3, b0, b1) \
    asm volatile("mma.sync.aligned.m16n8k16.row.col.f32.bf16.bf16.f32 " \
        "{%0,%1,%2,%3}, {%4,%5,%6,%7}, {%8,%9}, {%0,%1,%2,%3};" \
        : "+f"((c)[0]), "+f"((c)[1]), "+f"((c)[2]), "+f"((c)[3]) \
        : "r"(a0), "r"(a1), "r"(a2), "r"(a3), "r"(b0), "r"(b1))

// ============================================================================
// prep_w: W1 (k,n) and Wc1[5:,:] (k,n) -> bf16 hi/lo images [n][k], stride 136
// ============================================================================
__global__ void prep_w(const float* __restrict__ W1, const float* __restrict__ Wc1) {
    int idx = blockIdx.x * 256 + threadIdx.x;     // 16 blocks x 256 = 4096
    for (int i = idx; i < 32768; i += 4096) {
        int mat = i >> 14;
        int k = (i >> 7) & 127;
        int n = i & 127;
        float v = mat ? Wc1[(5 + k) * 128 + n] : W1[k * 128 + n];
        __nv_bfloat16 hv = __float2bfloat16(v);
        __nv_bfloat16 lv = __float2bfloat16(v - __bfloat162float(hv));
        int o = n * 136 + k;
        if (mat) { g_B2h[o] = hv; g_B2l[o] = lv; }
        else     { g_B1h[o] = hv; g_B1l[o] = lv; }
    }
}

// ============================================================================
// p1_mma: one 128-row tile per CTA, 256 threads (8 warps x m16 slices).
//   GEMM1 (mma.sync bf16 3-term): h_acc = x @ W1
//   epilogue A: +b1, LN (4-lane shfl), exact gelu; bx -> g_bx;
//               h repacked to bf16 hi/lo A-fragments IN REGISTERS
//   GEMM2: u_acc = h @ Wc1[5:,:]  (A from regs, B from SMEM)
//   epilogue B: +bc1 -> g_u (float2 stores)
// ============================================================================
#define OFF_AH   0
#define OFF_AL   34816
#define OFF_B1H  69632
#define OFF_B1L  104448
#define OFF_B2H  139264
#define OFF_B2L  174080
#define OFF_PAR  208896
#define OFF_SB1  (OFF_PAR + 0)
#define OFF_LNG  (OFF_PAR + 512)
#define OFF_LNB  (OFF_PAR + 1024)
#define OFF_BC1  (OFF_PAR + 1536)
#define OFF_WINN (OFF_PAR + 2048)   // 2560 B
#define SMEM_P1  (OFF_PAR + 4608)   // 213504 B

__global__ void __launch_bounds__(256, 1)
p1_mma(const float* __restrict__ x,    const float* __restrict__ b1,
       const float* __restrict__ ln_g, const float* __restrict__ ln_b,
       const float* __restrict__ Winn, const float* __restrict__ binn,
       const float* __restrict__ bc1)
{
    extern __shared__ char sm[];
    const int tid = threadIdx.x;
    const int wid = tid >> 5, lane = tid & 31;
    const int g = lane >> 2, q = lane & 3;
    const int row0 = blockIdx.x * 128;

    uint16_t* pAh = (uint16_t*)(sm + OFF_AH);
    uint16_t* pAl = (uint16_t*)(sm + OFF_AL);
    const uint16_t* pB1h = (const uint16_t*)(sm + OFF_B1H);
    const uint16_t* pB1l = (const uint16_t*)(sm + OFF_B1L);
    const uint16_t* pB2h = (const uint16_t*)(sm + OFF_B2H);
    const uint16_t* pB2l = (const uint16_t*)(sm + OFF_B2L);

    // ---- loads: params, weight images, x hi/lo split ----
    if (tid < 128) {
        ((float*)(sm + OFF_SB1))[tid] = b1[tid];
        ((float*)(sm + OFF_LNG))[tid] = ln_g[tid];
        ((float*)(sm + OFF_LNB))[tid] = ln_b[tid];
        ((float*)(sm + OFF_BC1))[tid] = bc1[tid];
    }
    for (int i = tid; i < 640; i += 256) ((float*)(sm + OFF_WINN))[i] = Winn[i];
    {
        const uint4* s1h = (const uint4*)g_B1h; const uint4* s1l = (const uint4*)g_B1l;
        const uint4* s2h = (const uint4*)g_B2h; const uint4* s2l = (const uint4*)g_B2l;
        uint4* d1h = (uint4*)pB1h; uint4* d1l = (uint4*)pB1l;
        uint4* d2h = (uint4*)pB2h; uint4* d2l = (uint4*)pB2l;
        for (int i = tid; i < 2176; i += 256) {
            d1h[i] = s1h[i]; d1l[i] = s1l[i]; d2h[i] = s2h[i]; d2l[i] = s2l[i];
        }
    }
    {
        const float4* xt = (const float4*)(x + (size_t)row0 * 128);
        for (int i = tid; i < 4096; i += 256) {
            float4 v = xt[i];
            int row = i >> 5, k4 = (i & 31) * 4;
            unsigned h0, l0, h1, l1;
            split2(v.x, v.y, h0, l0);
            split2(v.z, v.w, h1, l1);
            *(uint2*)&pAh[row * 136 + k4] = make_uint2(h0, h1);
            *(uint2*)&pAl[row * 136 + k4] = make_uint2(l0, l1);
        }
    }
    __syncthreads();

    const int rA = wid * 16 + g;      // tile-local rows this thread owns
    const int rB = rA + 8;

    // ---- GEMM1: acc = x @ W1 (3-term bf16 split) ----
    float acc[16][4];
#pragma unroll
    for (int nc = 0; nc < 16; nc++)
#pragma unroll
        for (int j = 0; j < 4; j++) acc[nc][j] = 0.f;

#pragma unroll 2
    for (int kc = 0; kc < 8; kc++) {
        const int k0 = kc * 16;
        unsigned ah0 = *(const unsigned*)&pAh[rA * 136 + k0 + 2 * q];
        unsigned ah1 = *(const unsigned*)&pAh[rB * 136 + k0 + 2 * q];
        unsigned ah2 = *(const unsigned*)&pAh[rA * 136 + k0 + 8 + 2 * q];
        unsigned ah3 = *(const unsigned*)&pAh[rB * 136 + k0 + 8 + 2 * q];
        unsigned al0 = *(const unsigned*)&pAl[rA * 136 + k0 + 2 * q];
        unsigned al1 = *(const unsigned*)&pAl[rB * 136 + k0 + 2 * q];
        unsigned al2 = *(const unsigned*)&pAl[rA * 136 + k0 + 8 + 2 * q];
        unsigned al3 = *(const unsigned*)&pAl[rB * 136 + k0 + 8 + 2 * q];
#pragma unroll
        for (int nc = 0; nc < 16; nc++) {
            const int nb = (nc * 8 + g) * 136 + k0 + 2 * q;
            unsigned bh0 = *(const unsigned*)&pB1h[nb];
            unsigned bh1 = *(const unsigned*)&pB1h[nb + 8];
            unsigned bl0 = *(const unsigned*)&pB1l[nb];
            unsigned bl1 = *(const unsigned*)&pB1l[nb + 8];
            MMA16816(acc[nc], ah0, ah1, ah2, ah3, bh0, bh1);
            MMA16816(acc[nc], ah0, ah1, ah2, ah3, bl0, bl1);
            MMA16816(acc[nc], al0, al1, al2, al3, bh0, bh1);
        }
    }

    // ---- Epilogue A: +b1, LN, exact gelu, bx, repack to GEMM2 A-frags ----
    const float* sB1 = (const float*)(sm + OFF_SB1);
    const float* sLG = (const float*)(sm + OFF_LNG);
    const float* sLB = (const float*)(sm + OFF_LNB);
    const float* sWn = (const float*)(sm + OFF_WINN);

    float sumA = 0.f, sqA = 0.f, sumB = 0.f, sqB = 0.f;
#pragma unroll
    for (int nc = 0; nc < 16; nc++) {
        const int c0 = nc * 8 + 2 * q;
        float v0 = acc[nc][0] + sB1[c0], v1 = acc[nc][1] + sB1[c0 + 1];
        float v2 = acc[nc][2] + sB1[c0], v3 = acc[nc][3] + sB1[c0 + 1];
        acc[nc][0] = v0; acc[nc][1] = v1; acc[nc][2] = v2; acc[nc][3] = v3;
        sumA += v0 + v1; sqA = fmaf(v0, v0, fmaf(v1, v1, sqA));
        sumB += v2 + v3; sqB = fmaf(v2, v2, fmaf(v3, v3, sqB));
    }
#pragma unroll
    for (int off = 1; off <= 2; off <<= 1) {
        sumA += __shfl_xor_sync(0xffffffffu, sumA, off);
        sqA  += __shfl_xor_sync(0xffffffffu, sqA,  off);
        sumB += __shfl_xor_sync(0xffffffffu, sumB, off);
        sqB  += __shfl_xor_sync(0xffffffffu, sqB,  off);
    }
    const float muA = sumA * 0.0078125f;
    const float rsA = rsqrtf(sqA * 0.0078125f - muA * muA + 1e-5f);
    const float muB = sumB * 0.0078125f;
    const float rsB = rsqrtf(sqB * 0.0078125f - muB * muB + 1e-5f);

    float bxA[5] = {0, 0, 0, 0, 0}, bxB[5] = {0, 0, 0, 0, 0};
#pragma unroll
    for (int nc = 0; nc < 16; nc++) {
        const int c0 = nc * 8 + 2 * q;
        float h0 = gelu_exact((acc[nc][0] - muA) * rsA * sLG[c0]     + sLB[c0]);
        float h1 = gelu_exact((acc[nc][1] - muA) * rsA * sLG[c0 + 1] + sLB[c0 + 1]);
        float h2 = gelu_exact((acc[nc][2] - muB) * rsB * sLG[c0]     + sLB[c0]);
        float h3 = gelu_exact((acc[nc][3] - muB) * rsB * sLG[c0 + 1] + sLB[c0 + 1]);
        acc[nc][0] = h0; acc[nc][1] = h1; acc[nc][2] = h2; acc[nc][3] = h3;
#pragma unroll
        for (int j = 0; j < 5; j++) {
            bxA[j] = fmaf(h0, sWn[c0 * 5 + j], fmaf(h1, sWn[(c0 + 1) * 5 + j], bxA[j]));
            bxB[j] = fmaf(h2, sWn[c0 * 5 + j], fmaf(h3, sWn[(c0 + 1) * 5 + j], bxB[j]));
        }
    }
#pragma unroll
    for (int off = 1; off <= 2; off <<= 1)
#pragma unroll
        for (int j = 0; j < 5; j++) {
            bxA[j] += __shfl_xor_sync(0xffffffffu, bxA[j], off);
            bxB[j] += __shfl_xor_sync(0xffffffffu, bxB[j], off);
        }
    if (q == 0) {
#pragma unroll
        for (int j = 0; j < 5; j++) {
            float bn = __ldg(&binn[j]);
            g_bx[(size_t)(row0 + rA) * 8 + j] = bxA[j] + bn;
            g_bx[(size_t)(row0 + rB) * 8 + j] = bxB[j] + bn;
        }
    }

    // repack h (in acc) into GEMM2 A-fragments (registers only, no SMEM)
    unsigned fh[8][4], fl[8][4];
#pragma unroll
    for (int kc = 0; kc < 8; kc++) {
        split2(acc[2*kc][0],     acc[2*kc][1],     fh[kc][0], fl[kc][0]); // (rA, k lo)
        split2(acc[2*kc][2],     acc[2*kc][3],     fh[kc][1], fl[kc][1]); // (rB, k lo)
        split2(acc[2*kc + 1][0], acc[2*kc + 1][1], fh[kc][2], fl[kc][2]); // (rA, k hi)
        split2(acc[2*kc + 1][2], acc[2*kc + 1][3], fh[kc][3], fl[kc][3]); // (rB, k hi)
    }

    // ---- GEMM2: acc = h @ Wc1[5:,:] ----
#pragma unroll
    for (int nc = 0; nc < 16; nc++)
#pragma unroll
        for (int j = 0; j < 4; j++) acc[nc][j] = 0.f;

#pragma unroll 2
    for (int kc = 0; kc < 8; kc++) {
        const int k0 = kc * 16;
#pragma unroll
        for (int nc = 0; nc < 16; nc++) {
            const int nb = (nc * 8 + g) * 136 + k0 + 2 * q;
            unsigned bh0 = *(const unsigned*)&pB2h[nb];
            unsigned bh1 = *(const unsigned*)&pB2h[nb + 8];
            unsigned bl0 = *(const unsigned*)&pB2l[nb];
            unsigned bl1 = *(const unsigned*)&pB2l[nb + 8];
            MMA16816(acc[nc], fh[kc][0], fh[kc][1], fh[kc][2], fh[kc][3], bh0, bh1);
            MMA16816(acc[nc], fh[kc][0], fh[kc][1], fh[kc][2], fh[kc][3], bl0, bl1);
            MMA16816(acc[nc], fl[kc][0], fl[kc][1], fl[kc][2], fl[kc][3], bh0, bh1);
        }
    }

    // ---- Epilogue B: +bc1 -> g_u ----
    const float* sBC = (const float*)(sm + OFF_BC1);
    const size_t gra = (size_t)(row0 + rA) * 128;
    const size_t grb = (size_t)(row0 + rB) * 128;
#pragma unroll
    for (int nc = 0; nc < 16; nc++) {
        const int c0 = nc * 8 + 2 * q;
        float bA = sBC[c0], bB = sBC[c0 + 1];
        *(float2*)&g_u[gra + c0] = make_float2(acc[nc][0] + bA, acc[nc][1] + bB);
        *(float2*)&g_u[grb + c0] = make_float2(acc[nc][2] + bA, acc[nc][3] + bB);
    }
}

// ============================================================================
// Phase 2: sequential scan. One warp per TWO batches (b, b+128): two
// independent chains interleaved to hide shfl/MUFU chain latency.
// 64 blocks x 2 warps; depth-4 software-pipelined register prefetch.
// ============================================================================
__global__ void __launch_bounds__(64)
p2_kernel(const float* __restrict__ Wc1, const float* __restrict__ Wc2,
          const float* __restrict__ bc2, const float* __restrict__ corr_scale,
          const float* __restrict__ raw_aL, const float* __restrict__ raw_aT,
          const float* __restrict__ raw_g,  const float* __restrict__ raw_aR,
          const float* __restrict__ omega,  float* __restrict__ out)
{
    const int warp = threadIdx.x >> 5, lane = threadIdx.x & 31;
    const int b0 = blockIdx.x * 2 + warp;
    const int bbs[2] = {b0, b0 + 128};

    const float aL = sigmoidf_(raw_aL[0]) * 0.15f + 0.85f;
    const float aT = sigmoidf_(raw_aT[0]) * 0.25f + 0.70f;
    const float gg = sigmoidf_(raw_g[0])  * 0.20f + 0.80f;
    const float aR = sigmoidf_(raw_aR[0]) * 0.40f;
    const float om = omega[0];
    const float gc = gg * cosf(om), gs = gg * sinf(om), ngs = -gs;
    const float cs = corr_scale[0];

    const int c0 = lane * 4;
    float Ws[5][4], Wo[4][5], bb[5];
#pragma unroll
    for (int i = 0; i < 5; i++)
#pragma unroll
        for (int c = 0; c < 4; c++) Ws[i][c] = Wc1[i*128 + c0 + c];
#pragma unroll
    for (int c = 0; c < 4; c++)
#pragma unroll
        for (int k = 0; k < 5; k++) Wo[c][k] = Wc2[(c0 + c)*5 + k];
#pragma unroll
    for (int k = 0; k < 5; k++) bb[k] = bc2[k];

    float s[2][5];
#pragma unroll
    for (int e = 0; e < 2; e++)
#pragma unroll
        for (int k = 0; k < 5; k++) s[e][k] = 0.f;

    const float4* up[2]; const float* bxp[2];
#pragma unroll
    for (int e = 0; e < 2; e++) {
        up[e]  = (const float4*)(g_u + (size_t)bbs[e] * NS * 128);
        bxp[e] = g_bx + (size_t)bbs[e] * NS * 8;
    }

    float4 ub[2][4], xb[2][4]; float x4b[2][4];
#pragma unroll
    for (int e = 0; e < 2; e++)
#pragma unroll
        for (int j = 0; j < 4; j++) {
            ub[e][j]  = up[e][j * 32 + lane];
            xb[e][j]  = *(const float4*)(bxp[e] + j * 8);
            x4b[e][j] = bxp[e][j * 8 + 4];
        }

    for (int t0 = 0; t0 < NS; t0 += 4) {
#pragma unroll
        for (int j = 0; j < 4; j++) {
            const int t = t0 + j;
            float4 u[2], x[2]; float x4[2];
#pragma unroll
            for (int e = 0; e < 2; e++) {
                u[e] = ub[e][j]; x[e] = xb[e][j]; x4[e] = x4b[e][j];
                ub[e][j]  = up[e][(t + 4) * 32 + lane];
                xb[e][j]  = *(const float4*)(bxp[e] + (t + 4) * 8);
                x4b[e][j] = bxp[e][(t + 4) * 8 + 4];
            }

            float l[2][5], m[2][4], p[2][5];
#pragma unroll
            for (int e = 0; e < 2; e++) {
                l[e][0] = fmaf(s[e][0], aL, x[e].x);
                l[e][1] = fmaf(s[e][1], aT, x[e].y);
                l[e][2] = fmaf(s[e][2], gc, fmaf(s[e][3], gs,  x[e].z));
                l[e][3] = fmaf(s[e][3], gc, fmaf(s[e][2], ngs, x[e].w));
                l[e][4] = fmaf(s[e][4], aR, x4[e]);
            }
#pragma unroll
            for (int e = 0; e < 2; e++) {
                float a0 = u[e].x, a1 = u[e].y, a2 = u[e].z, a3 = u[e].w;
#pragma unroll
                for (int i = 0; i < 5; i++) {
                    a0 = fmaf(l[e][i], Ws[i][0], a0);
                    a1 = fmaf(l[e][i], Ws[i][1], a1);
                    a2 = fmaf(l[e][i], Ws[i][2], a2);
                    a3 = fmaf(l[e][i], Ws[i][3], a3);
                }
                m[e][0] = gelu_fast(a0); m[e][1] = gelu_fast(a1);
                m[e][2] = gelu_fast(a2); m[e][3] = gelu_fast(a3);
            }
#pragma unroll
            for (int e = 0; e < 2; e++)
#pragma unroll
                for (int k = 0; k < 5; k++) {
                    float a = m[e][0] * Wo[0][k];
                    a = fmaf(m[e][1], Wo[1][k], a);
                    a = fmaf(m[e][2], Wo[2][k], a);
                    a = fmaf(m[e][3], Wo[3][k], a);
                    p[e][k] = a;
                }
#pragma unroll
            for (int off = 16; off; off >>= 1)
#pragma unroll
                for (int e = 0; e < 2; e++)
#pragma unroll
                    for (int k = 0; k < 5; k++)
                        p[e][k] += __shfl_xor_sync(0xffffffffu, p[e][k], off);
#pragma unroll
            for (int e = 0; e < 2; e++)
#pragma unroll
                for (int k = 0; k < 5; k++)
                    s[e][k] = fmaf(cs, tanh_fast(p[e][k] + bb[k]), l[e][k]);
        }
    }

    if (lane == 0) {
#pragma unroll
        for (int e = 0; e < 2; e++)
#pragma unroll
            for (int k = 0; k < 5; k++)
                out[bbs[e] * 5 + k] = s[e][k];
    }
}

// ============================================================================
extern "C" void kernel_launch(void* const* d_in, const int* in_sizes, int n_in,
                              void* d_out, int out_size)
{
    (void)in_sizes; (void)n_in; (void)out_size;
    const float* x    = (const float*)d_in[0];
    const float* W1   = (const float*)d_in[1];
    const float* b1   = (const float*)d_in[2];
    const float* ln_g = (const float*)d_in[3];
    const float* ln_b = (const float*)d_in[4];
    const float* Winn = (const float*)d_in[5];
    const float* binn = (const float*)d_in[6];
    const float* Wc1  = (const float*)d_in[7];
    const float* bc1  = (const float*)d_in[8];
    const float* Wc2  = (const float*)d_in[9];
    const float* bc2  = (const float*)d_in[10];
    const float* cscl = (const float*)d_in[11];
    const float* raL  = (const float*)d_in[12];
    const float* raT  = (const float*)d_in[13];
    const float* rg   = (const float*)d_in[14];
    const float* raR  = (const float*)d_in[15];
    const float* om   = (const float*)d_in[16];

    static int smem_set = 0;
    if (!smem_set) {
        cudaFuncSetAttribute(p1_mma, cudaFuncAttributeMaxDynamicSharedMemorySize, SMEM_P1);
        smem_set = 1;
    }

    prep_w<<<16, 256>>>(W1, Wc1);
    p1_mma<<<NROWS / 128, 256, SMEM_P1>>>(x, b1, ln_g, ln_b, Winn, binn, bc1);
    p2_kernel<<<64, 64>>>(Wc1, Wc2, bc2, cscl, raL, raT, rg, raR, om, (float*)d_out);
}

// round 6
// speedup vs baseline: 2.1753x; 1.2032x over previous
#include <cuda_runtime.h>
#include <cuda_bf16.h>
#include <math.h>
#include <stdint.h>

// Problem constants
#define NB   256
#define NS   1024
#define NROWS (NB * NS)   // 262144

// Scratch (device globals; padded by 4 rows for branch-free depth-4 prefetch)
__device__ float g_u[(size_t)NROWS * 128 + 512];
__device__ float g_bx[(size_t)NROWS * 8 + 32];
// bf16 hi/lo weight images, transposed to [n][k], row stride 136 elements
__device__ __nv_bfloat16 g_B1h[17408], g_B1l[17408], g_B2h[17408], g_B2l[17408];

// ---------------- math helpers ----------------
__device__ __forceinline__ float gelu_exact(float x) {
    return 0.5f * x * (1.0f + erff(x * 0.7071067811865475f));
}
__device__ __forceinline__ float sigmoidf_(float v) { return 1.0f / (1.0f + expf(-v)); }
__device__ __forceinline__ float tanh_fast(float x) {
    float y; asm("tanh.approx.f32 %0, %1;" : "=f"(y) : "f"(x)); return y;
}
__device__ __forceinline__ float gelu_fast(float x) {
    float x2 = x * x;
    float inner = 0.7978845608f * x * fmaf(0.044715f, x2, 1.0f);
    float t = tanh_fast(inner);
    float hx = 0.5f * x;
    return fmaf(hx, t, hx);
}
__device__ __forceinline__ unsigned pack_b2(__nv_bfloat16 a, __nv_bfloat16 b) {
    __nv_bfloat162 t = __halves2bfloat162(a, b);
    return *reinterpret_cast<unsigned*>(&t);
}
__device__ __forceinline__ void split2(float a, float b, unsigned& hi, unsigned& lo) {
    __nv_bfloat16 ha = __float2bfloat16(a), hb = __float2bfloat16(b);
    __nv_bfloat16 la = __float2bfloat16(a - __bfloat162float(ha));
    __nv_bfloat16 lb = __float2bfloat16(b - __bfloat162float(hb));
    hi = pack_b2(ha, hb); lo = pack_b2(la, lb);
}

#define MMA16816(c, a0, a1, a2, a3, b0, b1) \
    asm volatile("mma.sync.aligned.m16n8k16.row.col.f32.bf16.bf16.f32 " \
        "{%0,%1,%2,%3}, {%4,%5,%6,%7}, {%8,%9}, {%0,%1,%2,%3};" \
        : "+f"((c)[0]), "+f"((c)[1]), "+f"((c)[2]), "+f"((c)[3]) \
        : "r"(a0), "r"(a1), "r"(a2), "r"(a3), "r"(b0), "r"(b1))

// ============================================================================
// prep_w: W1 (k,n) and Wc1[5:,:] (k,n) -> bf16 hi/lo images [n][k], stride 136
// ============================================================================
__global__ void prep_w(const float* __restrict__ W1, const float* __restrict__ Wc1) {
    int idx = blockIdx.x * 256 + threadIdx.x;     // 16 blocks x 256 = 4096
    for (int i = idx; i < 32768; i += 4096) {
        int mat = i >> 14;
        int k = (i >> 7) & 127;
        int n = i & 127;
        float v = mat ? Wc1[(5 + k) * 128 + n] : W1[k * 128 + n];
        __nv_bfloat16 hv = __float2bfloat16(v);
        __nv_bfloat16 lv = __float2bfloat16(v - __bfloat162float(hv));
        int o = n * 136 + k;
        if (mat) { g_B2h[o] = hv; g_B2l[o] = lv; }
        else     { g_B1h[o] = hv; g_B1l[o] = lv; }
    }
}

// ============================================================================
// p1_mma (unchanged from R5): one 128-row tile per CTA, 256 threads.
// ============================================================================
#define OFF_AH   0
#define OFF_AL   34816
#define OFF_B1H  69632
#define OFF_B1L  104448
#define OFF_B2H  139264
#define OFF_B2L  174080
#define OFF_PAR  208896
#define OFF_SB1  (OFF_PAR + 0)
#define OFF_LNG  (OFF_PAR + 512)
#define OFF_LNB  (OFF_PAR + 1024)
#define OFF_BC1  (OFF_PAR + 1536)
#define OFF_WINN (OFF_PAR + 2048)   // 2560 B
#define SMEM_P1  (OFF_PAR + 4608)   // 213504 B

__global__ void __launch_bounds__(256, 1)
p1_mma(const float* __restrict__ x,    const float* __restrict__ b1,
       const float* __restrict__ ln_g, const float* __restrict__ ln_b,
       const float* __restrict__ Winn, const float* __restrict__ binn,
       const float* __restrict__ bc1)
{
    extern __shared__ char sm[];
    const int tid = threadIdx.x;
    const int wid = tid >> 5, lane = tid & 31;
    const int g = lane >> 2, q = lane & 3;
    const int row0 = blockIdx.x * 128;

    uint16_t* pAh = (uint16_t*)(sm + OFF_AH);
    uint16_t* pAl = (uint16_t*)(sm + OFF_AL);
    const uint16_t* pB1h = (const uint16_t*)(sm + OFF_B1H);
    const uint16_t* pB1l = (const uint16_t*)(sm + OFF_B1L);
    const uint16_t* pB2h = (const uint16_t*)(sm + OFF_B2H);
    const uint16_t* pB2l = (const uint16_t*)(sm + OFF_B2L);

    if (tid < 128) {
        ((float*)(sm + OFF_SB1))[tid] = b1[tid];
        ((float*)(sm + OFF_LNG))[tid] = ln_g[tid];
        ((float*)(sm + OFF_LNB))[tid] = ln_b[tid];
        ((float*)(sm + OFF_BC1))[tid] = bc1[tid];
    }
    for (int i = tid; i < 640; i += 256) ((float*)(sm + OFF_WINN))[i] = Winn[i];
    {
        const uint4* s1h = (const uint4*)g_B1h; const uint4* s1l = (const uint4*)g_B1l;
        const uint4* s2h = (const uint4*)g_B2h; const uint4* s2l = (const uint4*)g_B2l;
        uint4* d1h = (uint4*)pB1h; uint4* d1l = (uint4*)pB1l;
        uint4* d2h = (uint4*)pB2h; uint4* d2l = (uint4*)pB2l;
        for (int i = tid; i < 2176; i += 256) {
            d1h[i] = s1h[i]; d1l[i] = s1l[i]; d2h[i] = s2h[i]; d2l[i] = s2l[i];
        }
    }
    {
        const float4* xt = (const float4*)(x + (size_t)row0 * 128);
        for (int i = tid; i < 4096; i += 256) {
            float4 v = xt[i];
            int row = i >> 5, k4 = (i & 31) * 4;
            unsigned h0, l0, h1, l1;
            split2(v.x, v.y, h0, l0);
            split2(v.z, v.w, h1, l1);
            *(uint2*)&pAh[row * 136 + k4] = make_uint2(h0, h1);
            *(uint2*)&pAl[row * 136 + k4] = make_uint2(l0, l1);
        }
    }
    __syncthreads();

    const int rA = wid * 16 + g;
    const int rB = rA + 8;

    // ---- GEMM1: acc = x @ W1 (3-term bf16 split) ----
    float acc[16][4];
#pragma unroll
    for (int nc = 0; nc < 16; nc++)
#pragma unroll
        for (int j = 0; j < 4; j++) acc[nc][j] = 0.f;

#pragma unroll 2
    for (int kc = 0; kc < 8; kc++) {
        const int k0 = kc * 16;
        unsigned ah0 = *(const unsigned*)&pAh[rA * 136 + k0 + 2 * q];
        unsigned ah1 = *(const unsigned*)&pAh[rB * 136 + k0 + 2 * q];
        unsigned ah2 = *(const unsigned*)&pAh[rA * 136 + k0 + 8 + 2 * q];
        unsigned ah3 = *(const unsigned*)&pAh[rB * 136 + k0 + 8 + 2 * q];
        unsigned al0 = *(const unsigned*)&pAl[rA * 136 + k0 + 2 * q];
        unsigned al1 = *(const unsigned*)&pAl[rB * 136 + k0 + 2 * q];
        unsigned al2 = *(const unsigned*)&pAl[rA * 136 + k0 + 8 + 2 * q];
        unsigned al3 = *(const unsigned*)&pAl[rB * 136 + k0 + 8 + 2 * q];
#pragma unroll
        for (int nc = 0; nc < 16; nc++) {
            const int nb = (nc * 8 + g) * 136 + k0 + 2 * q;
            unsigned bh0 = *(const unsigned*)&pB1h[nb];
            unsigned bh1 = *(const unsigned*)&pB1h[nb + 8];
            unsigned bl0 = *(const unsigned*)&pB1l[nb];
            unsigned bl1 = *(const unsigned*)&pB1l[nb + 8];
            MMA16816(acc[nc], ah0, ah1, ah2, ah3, bh0, bh1);
            MMA16816(acc[nc], ah0, ah1, ah2, ah3, bl0, bl1);
            MMA16816(acc[nc], al0, al1, al2, al3, bh0, bh1);
        }
    }

    // ---- Epilogue A ----
    const float* sB1 = (const float*)(sm + OFF_SB1);
    const float* sLG = (const float*)(sm + OFF_LNG);
    const float* sLB = (const float*)(sm + OFF_LNB);
    const float* sWn = (const float*)(sm + OFF_WINN);

    float sumA = 0.f, sqA = 0.f, sumB = 0.f, sqB = 0.f;
#pragma unroll
    for (int nc = 0; nc < 16; nc++) {
        const int c0 = nc * 8 + 2 * q;
        float v0 = acc[nc][0] + sB1[c0], v1 = acc[nc][1] + sB1[c0 + 1];
        float v2 = acc[nc][2] + sB1[c0], v3 = acc[nc][3] + sB1[c0 + 1];
        acc[nc][0] = v0; acc[nc][1] = v1; acc[nc][2] = v2; acc[nc][3] = v3;
        sumA += v0 + v1; sqA = fmaf(v0, v0, fmaf(v1, v1, sqA));
        sumB += v2 + v3; sqB = fmaf(v2, v2, fmaf(v3, v3, sqB));
    }
#pragma unroll
    for (int off = 1; off <= 2; off <<= 1) {
        sumA += __shfl_xor_sync(0xffffffffu, sumA, off);
        sqA  += __shfl_xor_sync(0xffffffffu, sqA,  off);
        sumB += __shfl_xor_sync(0xffffffffu, sumB, off);
        sqB  += __shfl_xor_sync(0xffffffffu, sqB,  off);
    }
    const float muA = sumA * 0.0078125f;
    const float rsA = rsqrtf(sqA * 0.0078125f - muA * muA + 1e-5f);
    const float muB = sumB * 0.0078125f;
    const float rsB = rsqrtf(sqB * 0.0078125f - muB * muB + 1e-5f);

    float bxA[5] = {0, 0, 0, 0, 0}, bxB[5] = {0, 0, 0, 0, 0};
#pragma unroll
    for (int nc = 0; nc < 16; nc++) {
        const int c0 = nc * 8 + 2 * q;
        float h0 = gelu_exact((acc[nc][0] - muA) * rsA * sLG[c0]     + sLB[c0]);
        float h1 = gelu_exact((acc[nc][1] - muA) * rsA * sLG[c0 + 1] + sLB[c0 + 1]);
        float h2 = gelu_exact((acc[nc][2] - muB) * rsB * sLG[c0]     + sLB[c0]);
        float h3 = gelu_exact((acc[nc][3] - muB) * rsB * sLG[c0 + 1] + sLB[c0 + 1]);
        acc[nc][0] = h0; acc[nc][1] = h1; acc[nc][2] = h2; acc[nc][3] = h3;
#pragma unroll
        for (int j = 0; j < 5; j++) {
            bxA[j] = fmaf(h0, sWn[c0 * 5 + j], fmaf(h1, sWn[(c0 + 1) * 5 + j], bxA[j]));
            bxB[j] = fmaf(h2, sWn[c0 * 5 + j], fmaf(h3, sWn[(c0 + 1) * 5 + j], bxB[j]));
        }
    }
#pragma unroll
    for (int off = 1; off <= 2; off <<= 1)
#pragma unroll
        for (int j = 0; j < 5; j++) {
            bxA[j] += __shfl_xor_sync(0xffffffffu, bxA[j], off);
            bxB[j] += __shfl_xor_sync(0xffffffffu, bxB[j], off);
        }
    if (q == 0) {
#pragma unroll
        for (int j = 0; j < 5; j++) {
            float bn = __ldg(&binn[j]);
            g_bx[(size_t)(row0 + rA) * 8 + j] = bxA[j] + bn;
            g_bx[(size_t)(row0 + rB) * 8 + j] = bxB[j] + bn;
        }
    }

    // repack h into GEMM2 A-fragments (registers only)
    unsigned fh[8][4], fl[8][4];
#pragma unroll
    for (int kc = 0; kc < 8; kc++) {
        split2(acc[2*kc][0],     acc[2*kc][1],     fh[kc][0], fl[kc][0]);
        split2(acc[2*kc][2],     acc[2*kc][3],     fh[kc][1], fl[kc][1]);
        split2(acc[2*kc + 1][0], acc[2*kc + 1][1], fh[kc][2], fl[kc][2]);
        split2(acc[2*kc + 1][2], acc[2*kc + 1][3], fh[kc][3], fl[kc][3]);
    }

    // ---- GEMM2: acc = h @ Wc1[5:,:] ----
#pragma unroll
    for (int nc = 0; nc < 16; nc++)
#pragma unroll
        for (int j = 0; j < 4; j++) acc[nc][j] = 0.f;

#pragma unroll 2
    for (int kc = 0; kc < 8; kc++) {
        const int k0 = kc * 16;
#pragma unroll
        for (int nc = 0; nc < 16; nc++) {
            const int nb = (nc * 8 + g) * 136 + k0 + 2 * q;
            unsigned bh0 = *(const unsigned*)&pB2h[nb];
            unsigned bh1 = *(const unsigned*)&pB2h[nb + 8];
            unsigned bl0 = *(const unsigned*)&pB2l[nb];
            unsigned bl1 = *(const unsigned*)&pB2l[nb + 8];
            MMA16816(acc[nc], fh[kc][0], fh[kc][1], fh[kc][2], fh[kc][3], bh0, bh1);
            MMA16816(acc[nc], fh[kc][0], fh[kc][1], fh[kc][2], fh[kc][3], bl0, bl1);
            MMA16816(acc[nc], fl[kc][0], fl[kc][1], fl[kc][2], fl[kc][3], bh0, bh1);
        }
    }

    // ---- Epilogue B: +bc1 -> g_u ----
    const float* sBC = (const float*)(sm + OFF_BC1);
    const size_t gra = (size_t)(row0 + rA) * 128;
    const size_t grb = (size_t)(row0 + rB) * 128;
#pragma unroll
    for (int nc = 0; nc < 16; nc++) {
        const int c0 = nc * 8 + 2 * q;
        float bA = sBC[c0], bB = sBC[c0 + 1];
        *(float2*)&g_u[gra + c0] = make_float2(acc[nc][0] + bA, acc[nc][1] + bB);
        *(float2*)&g_u[grb + c0] = make_float2(acc[nc][2] + bA, acc[nc][3] + bB);
    }
}

// ============================================================================
// Phase 2: R3 body (known-good math), but ONE warp per block, 256 blocks ->
// chains spread over all 148 SMs (<=2 warps/SM), removing per-SM SHFL/L1tex
// contention that 4-warps-on-64-SMs had.
// ============================================================================
__global__ void __launch_bounds__(32)
p2_kernel(const float* __restrict__ Wc1, const float* __restrict__ Wc2,
          const float* __restrict__ bc2, const float* __restrict__ corr_scale,
          const float* __restrict__ raw_aL, const float* __restrict__ raw_aT,
          const float* __restrict__ raw_g,  const float* __restrict__ raw_aR,
          const float* __restrict__ omega,  float* __restrict__ out)
{
    const int lane = threadIdx.x & 31;
    const int b = blockIdx.x;

    const float aL = sigmoidf_(raw_aL[0]) * 0.15f + 0.85f;
    const float aT = sigmoidf_(raw_aT[0]) * 0.25f + 0.70f;
    const float gg = sigmoidf_(raw_g[0])  * 0.20f + 0.80f;
    const float aR = sigmoidf_(raw_aR[0]) * 0.40f;
    const float om = omega[0];
    const float gc = gg * cosf(om), gs = gg * sinf(om), ngs = -gs;
    const float cs = corr_scale[0];

    const int c0 = lane * 4;
    float Ws[5][4], Wo[4][5], bb[5];
#pragma unroll
    for (int i = 0; i < 5; i++)
#pragma unroll
        for (int c = 0; c < 4; c++) Ws[i][c] = Wc1[i*128 + c0 + c];
#pragma unroll
    for (int c = 0; c < 4; c++)
#pragma unroll
        for (int k = 0; k < 5; k++) Wo[c][k] = Wc2[(c0 + c)*5 + k];
#pragma unroll
    for (int k = 0; k < 5; k++) bb[k] = bc2[k];

    float s0 = 0.f, s1 = 0.f, s2 = 0.f, s3 = 0.f, s4 = 0.f;
    const float4* up  = (const float4*)(g_u + (size_t)b * NS * 128);
    const float*  bxp = g_bx + (size_t)b * NS * 8;

    // depth-4 rotating prefetch buffers
    float4 ub[4], xb[4]; float x4b[4];
#pragma unroll
    for (int j = 0; j < 4; j++) {
        ub[j]  = up[j * 32 + lane];
        xb[j]  = *(const float4*)(bxp + j * 8);
        x4b[j] = bxp[j * 8 + 4];
    }

    for (int t0 = 0; t0 < NS; t0 += 4) {
#pragma unroll
        for (int j = 0; j < 4; j++) {
            const int t = t0 + j;
            const float4 u = ub[j];
            const float4 x = xb[j];
            const float  x4 = x4b[j];
            ub[j]  = up[(t + 4) * 32 + lane];
            xb[j]  = *(const float4*)(bxp + (t + 4) * 8);
            x4b[j] = bxp[(t + 4) * 8 + 4];

            float l0 = fmaf(s0, aL, x.x);
            float l1 = fmaf(s1, aT, x.y);
            float l2 = fmaf(s2, gc, fmaf(s3, gs,  x.z));
            float l3 = fmaf(s3, gc, fmaf(s2, ngs, x.w));
            float l4 = fmaf(s4, aR, x4);

            float a0 = u.x, a1 = u.y, a2 = u.z, a3 = u.w;
            a0 = fmaf(l0, Ws[0][0], a0); a1 = fmaf(l0, Ws[0][1], a1);
            a2 = fmaf(l0, Ws[0][2], a2); a3 = fmaf(l0, Ws[0][3], a3);
            a0 = fmaf(l1, Ws[1][0], a0); a1 = fmaf(l1, Ws[1][1], a1);
            a2 = fmaf(l1, Ws[1][2], a2); a3 = fmaf(l1, Ws[1][3], a3);
            a0 = fmaf(l2, Ws[2][0], a0); a1 = fmaf(l2, Ws[2][1], a1);
            a2 = fmaf(l2, Ws[2][2], a2); a3 = fmaf(l2, Ws[2][3], a3);
            a0 = fmaf(l3, Ws[3][0], a0); a1 = fmaf(l3, Ws[3][1], a1);
            a2 = fmaf(l3, Ws[3][2], a2); a3 = fmaf(l3, Ws[3][3], a3);
            a0 = fmaf(l4, Ws[4][0], a0); a1 = fmaf(l4, Ws[4][1], a1);
            a2 = fmaf(l4, Ws[4][2], a2); a3 = fmaf(l4, Ws[4][3], a3);

            float m0 = gelu_fast(a0);
            float m1 = gelu_fast(a1);
            float m2 = gelu_fast(a2);
            float m3 = gelu_fast(a3);

            float p0 = m0*Wo[0][0], p1 = m0*Wo[0][1], p2 = m0*Wo[0][2],
                  p3 = m0*Wo[0][3], p4 = m0*Wo[0][4];
            p0 = fmaf(m1, Wo[1][0], p0); p1 = fmaf(m1, Wo[1][1], p1);
            p2 = fmaf(m1, Wo[1][2], p2); p3 = fmaf(m1, Wo[1][3], p3);
            p4 = fmaf(m1, Wo[1][4], p4);
            p0 = fmaf(m2, Wo[2][0], p0); p1 = fmaf(m2, Wo[2][1], p1);
            p2 = fmaf(m2, Wo[2][2], p2); p3 = fmaf(m2, Wo[2][3], p3);
            p4 = fmaf(m2, Wo[2][4], p4);
            p0 = fmaf(m3, Wo[3][0], p0); p1 = fmaf(m3, Wo[3][1], p1);
            p2 = fmaf(m3, Wo[3][2], p2); p3 = fmaf(m3, Wo[3][3], p3);
            p4 = fmaf(m3, Wo[3][4], p4);

#pragma unroll
            for (int off = 16; off; off >>= 1) {
                p0 += __shfl_xor_sync(0xffffffffu, p0, off);
                p1 += __shfl_xor_sync(0xffffffffu, p1, off);
                p2 += __shfl_xor_sync(0xffffffffu, p2, off);
                p3 += __shfl_xor_sync(0xffffffffu, p3, off);
                p4 += __shfl_xor_sync(0xffffffffu, p4, off);
            }
            s0 = fmaf(cs, tanh_fast(p0 + bb[0]), l0);
            s1 = fmaf(cs, tanh_fast(p1 + bb[1]), l1);
            s2 = fmaf(cs, tanh_fast(p2 + bb[2]), l2);
            s3 = fmaf(cs, tanh_fast(p3 + bb[3]), l3);
            s4 = fmaf(cs, tanh_fast(p4 + bb[4]), l4);
        }
    }

    if (lane == 0) {
        out[b*5+0] = s0; out[b*5+1] = s1; out[b*5+2] = s2;
        out[b*5+3] = s3; out[b*5+4] = s4;
    }
}

// ============================================================================
extern "C" void kernel_launch(void* const* d_in, const int* in_sizes, int n_in,
                              void* d_out, int out_size)
{
    (void)in_sizes; (void)n_in; (void)out_size;
    const float* x    = (const float*)d_in[0];
    const float* W1   = (const float*)d_in[1];
    const float* b1   = (const float*)d_in[2];
    const float* ln_g = (const float*)d_in[3];
    const float* ln_b = (const float*)d_in[4];
    const float* Winn = (const float*)d_in[5];
    const float* binn = (const float*)d_in[6];
    const float* Wc1  = (const float*)d_in[7];
    const float* bc1  = (const float*)d_in[8];
    const float* Wc2  = (const float*)d_in[9];
    const float* bc2  = (const float*)d_in[10];
    const float* cscl = (const float*)d_in[11];
    const float* raL  = (const float*)d_in[12];
    const float* raT  = (const float*)d_in[13];
    const float* rg   = (const float*)d_in[14];
    const float* raR  = (const float*)d_in[15];
    const float* om   = (const float*)d_in[16];

    static int smem_set = 0;
    if (!smem_set) {
        cudaFuncSetAttribute(p1_mma, cudaFuncAttributeMaxDynamicSharedMemorySize, SMEM_P1);
        smem_set = 1;
    }

    prep_w<<<16, 256>>>(W1, Wc1);
    p1_mma<<<NROWS / 128, 256, SMEM_P1>>>(x, b1, ln_g, ln_b, Winn, binn, bc1);
    p2_kernel<<<NB, 32>>>(Wc1, Wc2, bc2, cscl, raL, raT, rg, raR, om, (float*)d_out);
}